// round 2
// baseline (speedup 1.0000x reference)
#include <cuda_runtime.h>
#include <math.h>

#define NVOX 100000
#define CDIM 64
#define C4 256
#define KKTOT 343
#define KC 49
#define TILE 128
#define NT 256
#define NBLK ((NVOX + TILE - 1) / TILE)   // 782

// ---- static scratch (no allocations allowed in kernel_launch) ----
__device__ float g_x[(size_t)NVOX * CDIM];          // conv output (pre-GN)
__device__ float g_y[(size_t)NVOX * C4];            // pw1 output (post-ReLU)
__device__ float g_part1[NBLK * 8];                 // GN partials: s0,s1,q0,q1,cnt0,cnt1
__device__ float g_part2[NBLK * 2 * C4];            // GRN y^2 partials per (b, channel)
__device__ float g_gn[4];                           // mean0, rinv0, mean1, rinv1
__device__ float g_sj[2 * C4];                      // GRN scale per (b, channel)
__device__ float g_bterm[CDIM];                     // grn_beta @ w_pw2

// ================= conv kernel =================
// x[i] = sum_k feats[nbr[i,k]] @ w_dw[k]  (skip sentinel), + b_dw
__global__ void __launch_bounds__(NT) conv_kernel(
    const float* __restrict__ feats,
    const float* __restrict__ w_dw,
    const float* __restrict__ b_dw,
    const int*   __restrict__ nbr,
    const int*   __restrict__ batch_ids)
{
    extern __shared__ unsigned char smraw[];
    float* acc   = (float*)smraw;                 // TILE*CDIM
    float* fs    = acc + TILE * CDIM;             // TILE*CDIM (compacted gathered rows)
    float* ws    = fs + TILE * CDIM;              // CDIM*CDIM  [cin][cout]
    int*   sidx  = (int*)(ws + CDIM * CDIM);      // TILE*KC
    int*   vlist = sidx + TILE * KC;              // TILE packed (v<<17)|n
    int*   bs    = vlist + TILE;                  // TILE batch ids
    int*   nvp   = bs + TILE;

    const int tid = threadIdx.x;
    const int i0  = blockIdx.x * TILE;
    const int g   = tid >> 6;    // row group 0..3
    const int c   = tid & 63;    // output channel

    for (int t = tid; t < TILE * CDIM; t += NT) acc[t] = 0.f;
    if (tid < TILE) {
        int gi = i0 + tid;
        bs[tid] = (gi < NVOX) ? batch_ids[gi] : -1;
    }

    for (int kc = 0; kc < KKTOT / KC; kc++) {
        __syncthreads();
        // coalesced-ish chunk load of nbr rows (each element read exactly once)
        for (int t = tid; t < TILE * KC; t += NT) {
            int v = t / KC;
            int kk = t - v * KC;
            int gi = i0 + v;
            sidx[t] = (gi < NVOX) ? nbr[(long long)gi * KKTOT + kc * KC + kk] : NVOX;
        }
        for (int kk = 0; kk < KC; kk++) {
            const int k = kc * KC + kk;
            __syncthreads();   // prev compute done; sidx ready
            {   // stage weights (16KB) from L2
                const float4* w4 = (const float4*)(w_dw + (long long)k * CDIM * CDIM);
                float4* ws4 = (float4*)ws;
                #pragma unroll
                for (int t = 0; t < 4; t++) ws4[tid + t * NT] = w4[tid + t * NT];
            }
            if (tid == 0) *nvp = 0;
            __syncthreads();
            // compact valid rows (order irrelevant: distinct v per k)
            if (tid < TILE) {
                int n = sidx[tid * KC + kk];
                if (n < NVOX) {
                    int slot = atomicAdd(nvp, 1);
                    vlist[slot] = (tid << 17) | n;
                }
            }
            __syncthreads();
            const int m = *nvp;
            {   // gather valid feature rows into smem
                float4* fs4 = (float4*)fs;
                const float4* f4g = (const float4*)feats;
                for (int t = tid; t < (m << 4); t += NT) {
                    int e = t >> 4, p = t & 15;
                    int n = vlist[e] & 0x1FFFF;
                    fs4[(e << 4) + p] = f4g[(n << 4) + p];
                }
            }
            __syncthreads();
            // compute: each row group handles a contiguous quarter, 4 rows at a time
            int e0 = (m * g) >> 2;
            int e1 = (m * (g + 1)) >> 2;
            int e = e0;
            for (; e + 4 <= e1; e += 4) {
                int v0 = vlist[e] >> 17, v1 = vlist[e+1] >> 17,
                    v2 = vlist[e+2] >> 17, v3 = vlist[e+3] >> 17;
                const float4* f0 = (const float4*)(fs + (e+0) * CDIM);
                const float4* f1 = (const float4*)(fs + (e+1) * CDIM);
                const float4* f2 = (const float4*)(fs + (e+2) * CDIM);
                const float4* f3 = (const float4*)(fs + (e+3) * CDIM);
                float s0 = 0.f, s1 = 0.f, s2 = 0.f, s3 = 0.f;
                #pragma unroll
                for (int q = 0; q < 16; q++) {
                    float w0 = ws[(4*q+0) * CDIM + c];
                    float w1 = ws[(4*q+1) * CDIM + c];
                    float w2 = ws[(4*q+2) * CDIM + c];
                    float w3 = ws[(4*q+3) * CDIM + c];
                    float4 a0 = f0[q], a1 = f1[q], a2 = f2[q], a3 = f3[q];
                    s0 += a0.x*w0 + a0.y*w1 + a0.z*w2 + a0.w*w3;
                    s1 += a1.x*w0 + a1.y*w1 + a1.z*w2 + a1.w*w3;
                    s2 += a2.x*w0 + a2.y*w1 + a2.z*w2 + a2.w*w3;
                    s3 += a3.x*w0 + a3.y*w1 + a3.z*w2 + a3.w*w3;
                }
                acc[v0 * CDIM + c] += s0;
                acc[v1 * CDIM + c] += s1;
                acc[v2 * CDIM + c] += s2;
                acc[v3 * CDIM + c] += s3;
            }
            for (; e < e1; e++) {
                int v = vlist[e] >> 17;
                const float4* f = (const float4*)(fs + e * CDIM);
                float s = 0.f;
                #pragma unroll
                for (int q = 0; q < 16; q++) {
                    float4 a = f[q];
                    s += a.x * ws[(4*q+0)*CDIM + c];
                    s += a.y * ws[(4*q+1)*CDIM + c];
                    s += a.z * ws[(4*q+2)*CDIM + c];
                    s += a.w * ws[(4*q+3)*CDIM + c];
                }
                acc[v * CDIM + c] += s;
            }
        }
    }
    __syncthreads();
    // epilogue: bias, store, per-block GN partials (deterministic tree reduce)
    const float bias = b_dw[c];
    float s0 = 0.f, s1 = 0.f, q0 = 0.f, q1 = 0.f;
    int cnt0 = 0, cnt1 = 0;
    for (int v = g; v < TILE; v += 4) {
        int gi = i0 + v;
        if (gi >= NVOX) continue;
        float x = acc[v * CDIM + c] + bias;
        g_x[(long long)gi * CDIM + c] = x;
        if (bs[v] == 0) { s0 += x; q0 += x * x; cnt0++; }
        else           { s1 += x; q1 += x * x; cnt1++; }
    }
    __syncthreads();
    float* red = acc;                   // reuse smem
    int*   ired = (int*)(red + 4 * NT);
    red[tid]        = s0;
    red[NT + tid]   = s1;
    red[2*NT + tid] = q0;
    red[3*NT + tid] = q1;
    ired[tid]      = (c == 0) ? cnt0 : 0;
    ired[NT + tid] = (c == 0) ? cnt1 : 0;
    __syncthreads();
    for (int off = NT / 2; off > 0; off >>= 1) {
        if (tid < off) {
            red[tid]        += red[tid + off];
            red[NT + tid]   += red[NT + tid + off];
            red[2*NT + tid] += red[2*NT + tid + off];
            red[3*NT + tid] += red[3*NT + tid + off];
            ired[tid]       += ired[tid + off];
            ired[NT + tid]  += ired[NT + tid + off];
        }
        __syncthreads();
    }
    if (tid == 0) {
        float* p = g_part1 + blockIdx.x * 8;
        p[0] = red[0];      p[1] = red[NT];
        p[2] = red[2*NT];   p[3] = red[3*NT];
        p[4] = (float)ired[0];
        p[5] = (float)ired[NT];
    }
}

// ================= GN finalize (tiny, deterministic order) =================
__global__ void gn_finalize()
{
    __shared__ double sm[6];
    int tid = threadIdx.x;
    if (tid < 6) {
        double s = 0.0;
        for (int b = 0; b < NBLK; b++) s += (double)g_part1[b * 8 + tid];
        sm[tid] = s;
    }
    __syncthreads();
    if (tid == 0) {
        double cnt0 = sm[4] * CDIM, cnt1 = sm[5] * CDIM;
        double m0 = sm[0] / cnt0, m1 = sm[1] / cnt1;
        double v0 = sm[2] / cnt0 - m0 * m0;
        double v1 = sm[3] / cnt1 - m1 * m1;
        g_gn[0] = (float)m0;
        g_gn[1] = (float)(1.0 / sqrt(v0 + 1e-6));
        g_gn[2] = (float)m1;
        g_gn[3] = (float)(1.0 / sqrt(v1 + 1e-6));
    }
}

// ================= pw1: GN apply + x@w_pw1 + ReLU + y^2 partials =================
__global__ void __launch_bounds__(NT) pw1_kernel(
    const float* __restrict__ w_pw1,
    const float* __restrict__ gn_gamma,
    const float* __restrict__ gn_beta,
    const int*   __restrict__ batch_ids)
{
    extern __shared__ unsigned char smraw[];
    float* ws1 = (float*)smraw;              // CDIM*C4  [c][j]
    float* xs  = ws1 + CDIM * C4;            // TILE*CDIM
    int*   bs  = (int*)(xs + TILE * CDIM);   // TILE

    const int tid = threadIdx.x;
    const int i0 = blockIdx.x * TILE;
    const int rows = min(TILE, NVOX - i0);
    const int j = tid;

    for (int t = tid; t < CDIM * C4; t += NT) ws1[t] = w_pw1[t];
    if (tid < TILE) {
        int gi = i0 + tid;
        bs[tid] = (gi < NVOX) ? batch_ids[gi] : 0;
    }
    __syncthreads();
    const float mean0 = g_gn[0], rinv0 = g_gn[1], mean1 = g_gn[2], rinv1 = g_gn[3];
    for (int t = tid; t < TILE * CDIM; t += NT) {
        int v = t >> 6, cc = t & 63;
        float xv = 0.f;
        if (v < rows) {
            int b = bs[v];
            float x = g_x[(long long)(i0 + v) * CDIM + cc];
            float mn = (b == 0) ? mean0 : mean1;
            float ri = (b == 0) ? rinv0 : rinv1;
            xv = (x - mn) * ri * gn_gamma[cc] + gn_beta[cc];
        }
        xs[t] = xv;
    }
    __syncthreads();

    float pb0 = 0.f, pb1 = 0.f;
    for (int v0 = 0; v0 < TILE; v0 += 8) {
        float s[8];
        #pragma unroll
        for (int r = 0; r < 8; r++) s[r] = 0.f;
        for (int cc = 0; cc < CDIM; cc += 4) {
            float w0 = ws1[(cc+0) * C4 + j];
            float w1 = ws1[(cc+1) * C4 + j];
            float w2 = ws1[(cc+2) * C4 + j];
            float w3 = ws1[(cc+3) * C4 + j];
            #pragma unroll
            for (int r = 0; r < 8; r++) {
                float4 a = *(const float4*)&xs[(v0 + r) * CDIM + cc];
                s[r] += a.x*w0 + a.y*w1 + a.z*w2 + a.w*w3;
            }
        }
        #pragma unroll
        for (int r = 0; r < 8; r++) {
            int v = v0 + r;
            if (v < rows) {
                float y = fmaxf(s[r], 0.f);
                g_y[(long long)(i0 + v) * C4 + j] = y;
                if (bs[v] == 0) pb0 += y * y; else pb1 += y * y;
            }
        }
    }
    g_part2[blockIdx.x * (2 * C4) + j]      = pb0;
    g_part2[blockIdx.x * (2 * C4) + C4 + j] = pb1;
}

// ================= GRN finalize (tiny, deterministic) =================
__global__ void __launch_bounds__(C4) grn_finalize(
    const float* __restrict__ grn_gamma,
    const float* __restrict__ grn_beta,
    const float* __restrict__ w_pw2)
{
    __shared__ float red0[C4], red1[C4];
    const int j = threadIdx.x;
    double a0 = 0.0, a1 = 0.0;
    for (int b = 0; b < NBLK; b++) {
        a0 += (double)g_part2[b * (2 * C4) + j];
        a1 += (double)g_part2[b * (2 * C4) + C4 + j];
    }
    float gx0 = sqrtf((float)a0);
    float gx1 = sqrtf((float)a1);
    red0[j] = gx0; red1[j] = gx1;
    __syncthreads();
    for (int off = C4 / 2; off > 0; off >>= 1) {
        if (j < off) { red0[j] += red0[j + off]; red1[j] += red1[j + off]; }
        __syncthreads();
    }
    float m0 = red0[0] / (float)C4;
    float m1 = red1[0] / (float)C4;
    float nx0 = gx0 / (m0 + 1e-6f);
    float nx1 = gx1 / (m1 + 1e-6f);
    float gam = grn_gamma[j];
    g_sj[j]      = 1.f + gam * nx0;
    g_sj[C4 + j] = 1.f + gam * nx1;
    if (j < CDIM) {
        float s = 0.f;
        for (int jj = 0; jj < C4; jj++) s += grn_beta[jj] * w_pw2[jj * CDIM + j];
        g_bterm[j] = s;
    }
}

// ================= pw2: (y*sj)@w_pw2 + bterm + residual =================
__global__ void __launch_bounds__(NT) pw2_kernel(
    const float* __restrict__ feats,
    const float* __restrict__ w_pw2,
    const int*   __restrict__ batch_ids,
    float* __restrict__ out)
{
    extern __shared__ unsigned char smraw[];
    float* ys  = (float*)smraw;              // TILE*CDIM (one j-chunk, pre-scaled)
    float* w2s = ys + TILE * CDIM;           // CDIM*CDIM
    float* ssm = w2s + CDIM * CDIM;          // 2*C4
    int*   bs  = (int*)(ssm + 2 * C4);       // TILE

    const int tid = threadIdx.x;
    const int i0 = blockIdx.x * TILE;
    const int rows = min(TILE, NVOX - i0);
    const int c = tid & 63;
    const int g = tid >> 6;

    for (int t = tid; t < 2 * C4; t += NT) ssm[t] = g_sj[t];
    if (tid < TILE) {
        int gi = i0 + tid;
        bs[tid] = (gi < NVOX) ? batch_ids[gi] : 0;
    }

    float accr[32];
    #pragma unroll
    for (int r = 0; r < 32; r++) accr[r] = 0.f;

    for (int jc = 0; jc < 4; jc++) {
        __syncthreads();
        for (int t = tid; t < CDIM * CDIM; t += NT)
            w2s[t] = w_pw2[(jc * CDIM + (t >> 6)) * CDIM + (t & 63)];
        for (int t = tid; t < TILE * CDIM; t += NT) {
            int v = t >> 6, jj = t & 63;
            float y = 0.f;
            if (v < rows)
                y = g_y[(long long)(i0 + v) * C4 + jc * CDIM + jj]
                    * ssm[bs[v] * C4 + jc * CDIM + jj];
            ys[t] = y;
        }
        __syncthreads();
        #pragma unroll
        for (int r = 0; r < 32; r += 2) {
            const float* y0 = ys + (g + 4 * r) * CDIM;
            const float* y1 = ys + (g + 4 * r + 4) * CDIM;
            float s0 = accr[r], s1 = accr[r + 1];
            #pragma unroll
            for (int jj = 0; jj < CDIM; jj += 4) {
                float w0 = w2s[(jj+0) * CDIM + c];
                float w1 = w2s[(jj+1) * CDIM + c];
                float w2 = w2s[(jj+2) * CDIM + c];
                float w3 = w2s[(jj+3) * CDIM + c];
                float4 a0 = *(const float4*)(y0 + jj);
                float4 a1 = *(const float4*)(y1 + jj);
                s0 += a0.x*w0 + a0.y*w1 + a0.z*w2 + a0.w*w3;
                s1 += a1.x*w0 + a1.y*w1 + a1.z*w2 + a1.w*w3;
            }
            accr[r] = s0; accr[r + 1] = s1;
        }
    }
    const float bt = g_bterm[c];
    #pragma unroll
    for (int r = 0; r < 32; r++) {
        int v = g + 4 * r;
        int gi = i0 + v;
        if (v < rows)
            out[(long long)gi * CDIM + c] = feats[(long long)gi * CDIM + c] + accr[r] + bt;
    }
}

// ================= launch =================
#define CONV_SMEM 108544
#define PW1_SMEM  99328
#define PW2_SMEM  52224

extern "C" void kernel_launch(void* const* d_in, const int* in_sizes, int n_in,
                              void* d_out, int out_size)
{
    const float* feats     = (const float*)d_in[0];
    const float* w_dw      = (const float*)d_in[1];
    const float* b_dw      = (const float*)d_in[2];
    const float* gn_gamma  = (const float*)d_in[3];
    const float* gn_beta   = (const float*)d_in[4];
    const float* w_pw1     = (const float*)d_in[5];
    const float* grn_gamma = (const float*)d_in[6];
    const float* grn_beta  = (const float*)d_in[7];
    const float* w_pw2     = (const float*)d_in[8];
    const int*   nbr       = (const int*)d_in[9];
    const int*   batch_ids = (const int*)d_in[10];
    float* out = (float*)d_out;

    cudaFuncSetAttribute(conv_kernel, cudaFuncAttributeMaxDynamicSharedMemorySize, CONV_SMEM);
    cudaFuncSetAttribute(pw1_kernel,  cudaFuncAttributeMaxDynamicSharedMemorySize, PW1_SMEM);
    cudaFuncSetAttribute(pw2_kernel,  cudaFuncAttributeMaxDynamicSharedMemorySize, PW2_SMEM);

    conv_kernel<<<NBLK, NT, CONV_SMEM>>>(feats, w_dw, b_dw, nbr, batch_ids);
    gn_finalize<<<1, 32>>>();
    pw1_kernel<<<NBLK, NT, PW1_SMEM>>>(w_pw1, gn_gamma, gn_beta, batch_ids);
    grn_finalize<<<1, C4>>>(grn_gamma, grn_beta, w_pw2);
    pw2_kernel<<<NBLK, NT, PW2_SMEM>>>(feats, w_pw2, batch_ids, out);
}